// round 13
// baseline (speedup 1.0000x reference)
#include <cuda_runtime.h>
#include <math.h>

#define Bb 64
#define Tt 512
#define Ii 256
#define Hh 1024
#define BTH (Bb*Tt*Hh)
#define GB 128           // scan blocks: 4 batch-domains x 32 col-tiles
#define SCAN_SMEM (131072 + 65536 + 16384)   // ws + hs + red = 212992 B

typedef unsigned long long u64;

// ---------------- device state ----------------
__device__ float g_h[2][Hh*Bb];            // [buf][k*64 + b]  (transposed h)
__device__ __align__(512) uint4 g_flags4[32];  // 128 flag words; domain bt at [bt*8..bt*8+8)

// ---------------- f32x2 helpers ----------------
__device__ __forceinline__ u64 pack2(float x, float y){
    u64 r; asm("mov.b64 %0,{%1,%2};" : "=l"(r) : "f"(x), "f"(y)); return r;
}
__device__ __forceinline__ u64 dup2(float x){
    u64 r; asm("mov.b64 %0,{%1,%1};" : "=l"(r) : "f"(x)); return r;
}
__device__ __forceinline__ void unpack2(u64 v, float &x, float &y){
    asm("mov.b64 {%0,%1},%2;" : "=f"(x), "=f"(y) : "l"(v));
}
__device__ __forceinline__ u64 fma2(u64 a, u64 b, u64 c){
    u64 d; asm("fma.rn.f32x2 %0,%1,%2,%3;" : "=l"(d) : "l"(a), "l"(b), "l"(c)); return d;
}
__device__ __forceinline__ u64 add2(u64 a, u64 b){
    u64 d; asm("add.rn.f32x2 %0,%1,%2;" : "=l"(d) : "l"(a), "l"(b)); return d;
}

// ---------------- sync helpers ----------------
__device__ __forceinline__ void strel(unsigned* p, unsigned v){
    asm volatile("st.release.gpu.u32 [%0],%1;" :: "l"(p), "r"(v) : "memory");
}
// acquire-vector poll: orders subsequent loads after the matching st.release.gpu
__device__ __forceinline__ uint4 ldacq4(const unsigned* p){
    uint4 v;
    asm volatile("ld.acquire.gpu.v4.u32 {%0,%1,%2,%3},[%4];"
                 : "=r"(v.x), "=r"(v.y), "=r"(v.z), "=r"(v.w) : "l"(p) : "memory");
    return v;
}

// ---------------- init ----------------
__global__ void init_kernel(const float* __restrict__ h0){
    int idx = blockIdx.x * 256 + threadIdx.x;   // 0..65535
    int k = idx >> 6, b = idx & 63;
    g_h[0][idx] = h0[b * Hh + k];
    if (idx < GB) ((unsigned*)g_flags4)[idx] = 0u;
}

// ---------------- noop: ncu capture alignment ----------------
__global__ void noop_kernel(){}

// ---------------- phase 1: x_proj GEMM ----------------
__global__ __launch_bounds__(256) void xproj_kernel(
    const float* __restrict__ A,      // input  [B*T, I]
    const float* __restrict__ W,      // W_ih   [H, I]
    const float* __restrict__ bias,   // b_ih   [H]
    float* __restrict__ out)          // states [B*T, H]
{
    __shared__ float As[64*64];
    __shared__ float Bs[64*64];
    int tid = threadIdx.x;
    int m0 = blockIdx.y * 64, n0 = blockIdx.x * 64;
    int tx = tid & 15, ty = tid >> 4;

    u64 acc[4][2];
    #pragma unroll
    for (int i = 0; i < 4; i++){ acc[i][0] = 0ull; acc[i][1] = 0ull; }

    for (int kc = 0; kc < Ii; kc += 64){
        #pragma unroll
        for (int i = 0; i < 4; i++){
            int f = tid + i * 256;
            int m = f >> 4, kq = f & 15;
            float4 va = *(const float4*)(A + (m0 + m) * Ii + kc + kq * 4);
            float4 vb = *(const float4*)(W + (n0 + m) * Ii + kc + kq * 4);
            #pragma unroll
            for (int j = 0; j < 4; j++){
                int k = kq * 4 + j;
                int s = k * 64 + ((((m >> 2) ^ (k & 15)) << 2) | (m & 3));
                As[s] = ((const float*)&va)[j];
                Bs[s] = ((const float*)&vb)[j];
            }
        }
        __syncthreads();
        #pragma unroll 8
        for (int k = 0; k < 64; k++){
            int sw = k & 15;
            float4 a4 = *(const float4*)&As[k * 64 + ((ty ^ sw) << 2)];
            float4 b4 = *(const float4*)&Bs[k * 64 + ((tx ^ sw) << 2)];
            u64 b20 = pack2(b4.x, b4.y), b21 = pack2(b4.z, b4.w);
            u64 a2;
            a2 = dup2(a4.x); acc[0][0]=fma2(a2,b20,acc[0][0]); acc[0][1]=fma2(a2,b21,acc[0][1]);
            a2 = dup2(a4.y); acc[1][0]=fma2(a2,b20,acc[1][0]); acc[1][1]=fma2(a2,b21,acc[1][1]);
            a2 = dup2(a4.z); acc[2][0]=fma2(a2,b20,acc[2][0]); acc[2][1]=fma2(a2,b21,acc[2][1]);
            a2 = dup2(a4.w); acc[3][0]=fma2(a2,b20,acc[3][0]); acc[3][1]=fma2(a2,b21,acc[3][1]);
        }
        __syncthreads();
    }

    float4 bv = *(const float4*)(bias + n0 + tx * 4);
    #pragma unroll
    for (int i = 0; i < 4; i++){
        float x0, x1, x2, x3;
        unpack2(acc[i][0], x0, x1);
        unpack2(acc[i][1], x2, x3);
        float4 r = make_float4(x0 + bv.x, x1 + bv.y, x2 + bv.z, x3 + bv.w);
        *(float4*)(out + (size_t)(m0 + ty * 4 + i) * Hh + n0 + tx * 4) = r;
    }
}

// ---- per-warp chunk macros (chunk = 32 k-rows; block stages 16 batches) ----
#define CPASYNC_CHUNK(c) { \
    const int rb_ = rbase0 + (c) * 32; \
    _Pragma("unroll") \
    for (int i_ = 0; i_ < 4; i_++){ \
        int row_ = rb_ + srow + i_ * 8; \
        unsigned da_ = hs_addr + (unsigned)((row_ * 16 + sq * 4) * 4); \
        const float* ga_ = hgp + (size_t)row_ * 64; \
        asm volatile("cp.async.cg.shared.global [%0], [%1], 16;" :: "r"(da_), "l"(ga_)); \
    } \
    asm volatile("cp.async.commit_group;"); \
}
#define GEMM_CHUNK(c) { \
    const float* hp_ = &hs[(rbase0 + (c) * 32) * 16 + bg * 4]; \
    const float* wp_ = &ws[(rbase0 + (c) * 32) * 32 + cg * 4]; \
    _Pragma("unroll") \
    for (int kk_ = 0; kk_ < 32; kk_++){ \
        ulonglong2 hv_ = *(const ulonglong2*)(hp_ + kk_ * 16); \
        float4 w4_ = *(const float4*)(wp_ + kk_ * 32); \
        u64 w20_ = dup2(w4_.x), w21_ = dup2(w4_.y), w22_ = dup2(w4_.z), w23_ = dup2(w4_.w); \
        acc0 = fma2(hv_.x, w20_, acc0); acc1 = fma2(hv_.x, w21_, acc1); \
        acc2 = fma2(hv_.x, w22_, acc2); acc3 = fma2(hv_.x, w23_, acc3); \
        acc4 = fma2(hv_.y, w20_, acc4); acc5 = fma2(hv_.y, w21_, acc5); \
        acc6 = fma2(hv_.y, w22_, acc6); acc7 = fma2(hv_.y, w23_, acc7); \
    } \
}

// ---------------- phase 2: persistent scan, per-warp acquire-vector waits ----------------
__global__ __launch_bounds__(256, 1) void scan_kernel(
    const float* __restrict__ Whh,    // [H, H]
    const float* __restrict__ bhh,    // [H]
    float* __restrict__ out,          // states (xp in-place) + hidden tail
    int writeHidden)
{
    extern __shared__ float smf[];
    float* ws = smf;                         // [1024][32]  W slice (k-major)
    float* hs = smf + 1024 * 32;             // [1024][16]  h slice (k-major)
    u64*   red = (u64*)(smf + 1024 * 32 + 1024 * 16);   // [8][32][8]
    unsigned hs_addr = (unsigned)__cvta_generic_to_shared(hs);

    int tid = threadIdx.x;
    int blk = blockIdx.x;
    int ct = blk & 31;                // col tile (32 cols)
    int bt = blk >> 5;                // batch domain (16 batches)
    int c0 = ct * 32;
    int b0 = bt * 16;

    // prologue: resident W slice, transposed to [k][c_local]
    #pragma unroll
    for (int i = 0; i < 32; i++){
        int f = tid + i * 256;        // 0..8191 float4 slots (32 rows x 256)
        int cl = f >> 8;
        int kq = f & 255;
        float4 v = *(const float4*)(Whh + (c0 + cl) * Hh + kq * 4);
        int k = kq * 4;
        ws[(k + 0) * 32 + cl] = v.x;
        ws[(k + 1) * 32 + cl] = v.y;
        ws[(k + 2) * 32 + cl] = v.z;
        ws[(k + 3) * 32 + cl] = v.w;
    }

    int w    = tid >> 5;              // warp = k-slice (8 warps x 128 k)
    int lane = tid & 31;
    int bg = lane >> 3;               // 0..3  -> batch-pairs 2bg, 2bg+1
    int cg = lane & 7;                // 0..7  -> cols 4cg..4cg+3
    int srow = lane >> 2;             // staging: row-in-group-of-8
    int sq   = lane & 3;              // staging: float4 column (16 floats/row)
    int rbase0 = w * 128;

    // this warp's 4 producer flags: domain bt, col-tiles 4w..4w+3 (one aligned uint4)
    const unsigned* fp = (const unsigned*)&g_flags4[bt * 8 + w];
    unsigned* myflag = &((unsigned*)g_flags4)[blk];

    // epilogue mapping: thread -> (batch-pair p, col)
    int p   = tid >> 5;               // 0..7 batch-pair
    int col = tid & 31;               // 0..31 col
    int e_lane = ((p >> 1) << 3) | (col >> 2);
    int e_idx  = ((p & 1) << 2) | (col & 3);
    int gb = b0 + p * 2;              // global batch (even)
    int gc = c0 + col;                // global col
    float bhc = __ldg(bhh + gc);

    __syncthreads();                  // ws visible to all warps

    // first-step xp prefetch
    size_t o0 = ((size_t)gb * Tt + 0) * Hh + gc;
    size_t o1 = o0 + (size_t)Tt * Hh;
    float xp0 = out[o0];
    float xp1 = out[o1];

    for (int s = 0; s < Tt; s++){
        int cur = s & 1;
        const float* hgp = g_h[cur] + b0 + sq * 4;   // per-lane staging base

        // ---- wait for THIS warp's 4 producers (one acquire-vector poll, no fence) ----
        if (s > 0){
            unsigned need = (unsigned)s;
            int tries = 0;
            for (;;){
                uint4 f = ldacq4(fp);
                bool ok = (f.x >= need) & (f.y >= need) & (f.z >= need) & (f.w >= need);
                if (ok) break;
                if (++tries > 16) __nanosleep(32);
            }
        }

        // ---- stage via cp.async: 4 chunk-groups issued up-front ----
        CPASYNC_CHUNK(0);
        CPASYNC_CHUNK(1);
        CPASYNC_CHUNK(2);
        CPASYNC_CHUNK(3);

        // ---- GEMM: 128 k per warp, chunk waits interleaved ----
        u64 acc0 = 0, acc1 = 0, acc2 = 0, acc3 = 0, acc4 = 0, acc5 = 0, acc6 = 0, acc7 = 0;
        asm volatile("cp.async.wait_group 3;");
        __syncwarp();
        GEMM_CHUNK(0);
        asm volatile("cp.async.wait_group 2;");
        __syncwarp();
        GEMM_CHUNK(1);
        asm volatile("cp.async.wait_group 1;");
        __syncwarp();
        GEMM_CHUNK(2);
        asm volatile("cp.async.wait_group 0;");
        __syncwarp();
        GEMM_CHUNK(3);

        u64* rp = &red[(w * 32 + lane) * 8];
        rp[0] = acc0; rp[1] = acc1; rp[2] = acc2; rp[3] = acc3;
        rp[4] = acc4; rp[5] = acc5; rp[6] = acc6; rp[7] = acc7;
        __syncthreads();              // all warps done => block observed ALL 32 flags >= s

        // ---- reduce k-slices, fuse bias + xp + tanh ----
        u64 ssum = red[(0 * 32 + e_lane) * 8 + e_idx];
        #pragma unroll
        for (int ww = 1; ww < 8; ww++)
            ssum = add2(ssum, red[(ww * 32 + e_lane) * 8 + e_idx]);
        float lo, hi;
        unpack2(ssum, lo, hi);

        float v0 = tanhf(lo + bhc + xp0);
        float v1 = tanhf(hi + bhc + xp1);

        // h_next: the only cross-block-visible payload (WAR-safe: all flags >= s observed)
        float* hn = g_h[cur ^ 1];
        *(float2*)&hn[gc * 64 + gb] = make_float2(v0, v1);

        // ---- publish ----
        unsigned tgt = (unsigned)(s + 1);
        __syncthreads();                           // all hn writes done (CTA scope)
        if (tid == 0) strel(myflag, tgt);

        // ---- deferred block-local work (hides under consumers' progress) ----
        out[o0] = v0;
        out[o1] = v1;
        if (writeHidden && s == Tt - 1){
            out[(size_t)BTH + (size_t)gb * Hh + gc] = v0;
            out[(size_t)BTH + (size_t)(gb + 1) * Hh + gc] = v1;
        }
        if (s + 1 < Tt){
            o0 = ((size_t)gb * Tt + (s + 1)) * Hh + gc;
            o1 = o0 + (size_t)Tt * Hh;
            xp0 = out[o0];
            xp1 = out[o1];
        }
    }
}

// ---------------- launch ----------------
extern "C" void kernel_launch(void* const* d_in, const int* in_sizes, int n_in,
                              void* d_out, int out_size)
{
    const float* input = (const float*)d_in[0];   // [B,T,I]
    const float* h0    = (const float*)d_in[1];   // [B,H]
    const float* Wih   = (const float*)d_in[2];   // [H,I]
    const float* Whh   = (const float*)d_in[3];   // [H,H]
    const float* bih   = (const float*)d_in[4];   // [H]
    const float* bhh   = (const float*)d_in[5];   // [H]
    float* out = (float*)d_out;
    int writeHidden = (out_size >= BTH + Bb * Hh) ? 1 : 0;

    cudaFuncSetAttribute(scan_kernel, cudaFuncAttributeMaxDynamicSharedMemorySize, SCAN_SMEM);

    init_kernel<<<256, 256>>>(h0);
    xproj_kernel<<<dim3(16, 512), 256>>>(input, Wih, bih, out);
    noop_kernel<<<1, 32>>>();
    scan_kernel<<<GB, 256, SCAN_SMEM>>>(Whh, bhh, out, writeHidden);
}

// round 14
// speedup vs baseline: 1.1712x; 1.1712x over previous
#include <cuda_runtime.h>
#include <math.h>

#define Bb 64
#define Tt 512
#define Ii 256
#define Hh 1024
#define BTH (Bb*Tt*Hh)
#define GB 128           // scan blocks: 4 batch-domains x 32 col-tiles
#define SCAN_SMEM (131072 + 65536 + 16384)   // ws + hs + red = 212992 B

typedef unsigned long long u64;

// ---------------- device state ----------------
__device__ float g_h[2][Hh*Bb];        // [buf][k*64 + b]  (transposed h)
__device__ __align__(128) unsigned g_flags[GB];  // per-block step counter; domain = 1 line

// ---------------- f32x2 helpers ----------------
__device__ __forceinline__ u64 pack2(float x, float y){
    u64 r; asm("mov.b64 %0,{%1,%2};" : "=l"(r) : "f"(x), "f"(y)); return r;
}
__device__ __forceinline__ u64 dup2(float x){
    u64 r; asm("mov.b64 %0,{%1,%1};" : "=l"(r) : "f"(x)); return r;
}
__device__ __forceinline__ void unpack2(u64 v, float &x, float &y){
    asm("mov.b64 {%0,%1},%2;" : "=f"(x), "=f"(y) : "l"(v));
}
__device__ __forceinline__ u64 fma2(u64 a, u64 b, u64 c){
    u64 d; asm("fma.rn.f32x2 %0,%1,%2,%3;" : "=l"(d) : "l"(a), "l"(b), "l"(c)); return d;
}
__device__ __forceinline__ u64 add2(u64 a, u64 b){
    u64 d; asm("add.rn.f32x2 %0,%1,%2;" : "=l"(d) : "l"(a), "l"(b)); return d;
}

// ---------------- sync helpers ----------------
__device__ __forceinline__ void strel(unsigned* p, unsigned v){
    asm volatile("st.release.gpu.u32 [%0],%1;" :: "l"(p), "r"(v) : "memory");
}
__device__ __forceinline__ unsigned ldrelaxed(const unsigned* p){
    unsigned v;
    asm volatile("ld.relaxed.gpu.u32 %0,[%1];" : "=r"(v) : "l"(p) : "memory");
    return v;
}

// ---------------- init ----------------
__global__ void init_kernel(const float* __restrict__ h0){
    int idx = blockIdx.x * 256 + threadIdx.x;   // 0..65535
    int k = idx >> 6, b = idx & 63;
    g_h[0][idx] = h0[b * Hh + k];
    if (idx < GB) g_flags[idx] = 0u;
}

// ---------------- noop: ncu capture alignment ----------------
__global__ void noop_kernel(){}

// ---------------- phase 1: x_proj GEMM ----------------
__global__ __launch_bounds__(256) void xproj_kernel(
    const float* __restrict__ A,      // input  [B*T, I]
    const float* __restrict__ W,      // W_ih   [H, I]
    const float* __restrict__ bias,   // b_ih   [H]
    float* __restrict__ out)          // states [B*T, H]
{
    __shared__ float As[64*64];
    __shared__ float Bs[64*64];
    int tid = threadIdx.x;
    int m0 = blockIdx.y * 64, n0 = blockIdx.x * 64;
    int tx = tid & 15, ty = tid >> 4;

    u64 acc[4][2];
    #pragma unroll
    for (int i = 0; i < 4; i++){ acc[i][0] = 0ull; acc[i][1] = 0ull; }

    for (int kc = 0; kc < Ii; kc += 64){
        #pragma unroll
        for (int i = 0; i < 4; i++){
            int f = tid + i * 256;
            int m = f >> 4, kq = f & 15;
            float4 va = *(const float4*)(A + (m0 + m) * Ii + kc + kq * 4);
            float4 vb = *(const float4*)(W + (n0 + m) * Ii + kc + kq * 4);
            #pragma unroll
            for (int j = 0; j < 4; j++){
                int k = kq * 4 + j;
                int s = k * 64 + ((((m >> 2) ^ (k & 15)) << 2) | (m & 3));
                As[s] = ((const float*)&va)[j];
                Bs[s] = ((const float*)&vb)[j];
            }
        }
        __syncthreads();
        #pragma unroll 8
        for (int k = 0; k < 64; k++){
            int sw = k & 15;
            float4 a4 = *(const float4*)&As[k * 64 + ((ty ^ sw) << 2)];
            float4 b4 = *(const float4*)&Bs[k * 64 + ((tx ^ sw) << 2)];
            u64 b20 = pack2(b4.x, b4.y), b21 = pack2(b4.z, b4.w);
            u64 a2;
            a2 = dup2(a4.x); acc[0][0]=fma2(a2,b20,acc[0][0]); acc[0][1]=fma2(a2,b21,acc[0][1]);
            a2 = dup2(a4.y); acc[1][0]=fma2(a2,b20,acc[1][0]); acc[1][1]=fma2(a2,b21,acc[1][1]);
            a2 = dup2(a4.z); acc[2][0]=fma2(a2,b20,acc[2][0]); acc[2][1]=fma2(a2,b21,acc[2][1]);
            a2 = dup2(a4.w); acc[3][0]=fma2(a2,b20,acc[3][0]); acc[3][1]=fma2(a2,b21,acc[3][1]);
        }
        __syncthreads();
    }

    float4 bv = *(const float4*)(bias + n0 + tx * 4);
    #pragma unroll
    for (int i = 0; i < 4; i++){
        float x0, x1, x2, x3;
        unpack2(acc[i][0], x0, x1);
        unpack2(acc[i][1], x2, x3);
        float4 r = make_float4(x0 + bv.x, x1 + bv.y, x2 + bv.z, x3 + bv.w);
        *(float4*)(out + (size_t)(m0 + ty * 4 + i) * Hh + n0 + tx * 4) = r;
    }
}

// ---- per-warp chunk macros (chunk = 32 k-rows; block stages 16 batches) ----
#define CPASYNC_CHUNK(c) { \
    const int rb_ = rbase0 + (c) * 32; \
    _Pragma("unroll") \
    for (int i_ = 0; i_ < 4; i_++){ \
        int row_ = rb_ + srow + i_ * 8; \
        unsigned da_ = hs_addr + (unsigned)((row_ * 16 + sq * 4) * 4); \
        const float* ga_ = hgp + (size_t)row_ * 64; \
        asm volatile("cp.async.cg.shared.global [%0], [%1], 16;" :: "r"(da_), "l"(ga_)); \
    } \
    asm volatile("cp.async.commit_group;"); \
}
#define GEMM_CHUNK(c) { \
    const float* hp_ = &hs[(rbase0 + (c) * 32) * 16 + bg * 4]; \
    const float* wp_ = &ws[(rbase0 + (c) * 32) * 32 + cg * 4]; \
    _Pragma("unroll") \
    for (int kk_ = 0; kk_ < 32; kk_++){ \
        ulonglong2 hv_ = *(const ulonglong2*)(hp_ + kk_ * 16); \
        float4 w4_ = *(const float4*)(wp_ + kk_ * 32); \
        u64 w20_ = dup2(w4_.x), w21_ = dup2(w4_.y), w22_ = dup2(w4_.z), w23_ = dup2(w4_.w); \
        acc0 = fma2(hv_.x, w20_, acc0); acc1 = fma2(hv_.x, w21_, acc1); \
        acc2 = fma2(hv_.x, w22_, acc2); acc3 = fma2(hv_.x, w23_, acc3); \
        acc4 = fma2(hv_.y, w20_, acc4); acc5 = fma2(hv_.y, w21_, acc5); \
        acc6 = fma2(hv_.y, w22_, acc6); acc7 = fma2(hv_.y, w23_, acc7); \
    } \
}

// ---------------- phase 2: persistent scan, direct coalesced block-sweep ----------------
__global__ __launch_bounds__(256, 1) void scan_kernel(
    const float* __restrict__ Whh,    // [H, H]
    const float* __restrict__ bhh,    // [H]
    float* __restrict__ out,          // states (xp in-place) + hidden tail
    int writeHidden)
{
    extern __shared__ float smf[];
    float* ws = smf;                         // [1024][32]  W slice (k-major)
    float* hs = smf + 1024 * 32;             // [1024][16]  h slice (k-major)
    u64*   red = (u64*)(smf + 1024 * 32 + 1024 * 16);   // [8][32][8]
    unsigned hs_addr = (unsigned)__cvta_generic_to_shared(hs);

    int tid = threadIdx.x;
    int blk = blockIdx.x;
    int ct = blk & 31;                // col tile (32 cols)
    int bt = blk >> 5;                // batch domain (16 batches)
    int c0 = ct * 32;
    int b0 = bt * 16;

    // prologue: resident W slice, transposed to [k][c_local]
    #pragma unroll
    for (int i = 0; i < 32; i++){
        int f = tid + i * 256;        // 0..8191 float4 slots (32 rows x 256)
        int cl = f >> 8;
        int kq = f & 255;
        float4 v = *(const float4*)(Whh + (c0 + cl) * Hh + kq * 4);
        int k = kq * 4;
        ws[(k + 0) * 32 + cl] = v.x;
        ws[(k + 1) * 32 + cl] = v.y;
        ws[(k + 2) * 32 + cl] = v.z;
        ws[(k + 3) * 32 + cl] = v.w;
    }

    int w    = tid >> 5;              // warp = k-slice (8 warps x 128 k)
    int lane = tid & 31;
    int bg = lane >> 3;               // 0..3  -> batch-pairs 2bg, 2bg+1
    int cg = lane & 7;                // 0..7  -> cols 4cg..4cg+3
    int srow = lane >> 2;             // staging: row-in-group-of-8
    int sq   = lane & 3;              // staging: float4 column (16 floats/row)
    int rbase0 = w * 128;

    // epilogue mapping: thread -> (batch-pair p, col)
    int p   = tid >> 5;               // 0..7 batch-pair
    int col = tid & 31;               // 0..31 col
    int e_lane = ((p >> 1) << 3) | (col >> 2);
    int e_idx  = ((p & 1) << 2) | (col & 3);
    int gb = b0 + p * 2;              // global batch (even)
    int gc = c0 + col;                // global col
    float bhc = __ldg(bhh + gc);

    // barrier state: domain flags = one 128-B line; warp0 lane i watches flag i
    const unsigned* myflagline = g_flags + bt * 32 + lane;

    __syncthreads();                  // ws visible to all warps

    // first-step xp prefetch
    size_t o0 = ((size_t)gb * Tt + 0) * Hh + gc;
    size_t o1 = o0 + (size_t)Tt * Hh;
    float xp0 = out[o0];
    float xp1 = out[o1];

    for (int s = 0; s < Tt; s++){
        int cur = s & 1;
        const float* hgp = g_h[cur] + b0 + sq * 4;   // per-lane staging base

        // ---- stage via cp.async: 4 chunk-groups issued up-front ----
        CPASYNC_CHUNK(0);
        CPASYNC_CHUNK(1);
        CPASYNC_CHUNK(2);
        CPASYNC_CHUNK(3);

        // ---- GEMM: 128 k per warp, chunk waits interleaved ----
        u64 acc0 = 0, acc1 = 0, acc2 = 0, acc3 = 0, acc4 = 0, acc5 = 0, acc6 = 0, acc7 = 0;
        asm volatile("cp.async.wait_group 3;");
        __syncwarp();
        GEMM_CHUNK(0);
        asm volatile("cp.async.wait_group 2;");
        __syncwarp();
        GEMM_CHUNK(1);
        asm volatile("cp.async.wait_group 1;");
        __syncwarp();
        GEMM_CHUNK(2);
        asm volatile("cp.async.wait_group 0;");
        __syncwarp();
        GEMM_CHUNK(3);

        u64* rp = &red[(w * 32 + lane) * 8];
        rp[0] = acc0; rp[1] = acc1; rp[2] = acc2; rp[3] = acc3;
        rp[4] = acc4; rp[5] = acc5; rp[6] = acc6; rp[7] = acc7;
        __syncthreads();

        // ---- reduce k-slices, fuse bias + xp + tanh ----
        u64 ssum = red[(0 * 32 + e_lane) * 8 + e_idx];
        #pragma unroll
        for (int ww = 1; ww < 8; ww++)
            ssum = add2(ssum, red[(ww * 32 + e_lane) * 8 + e_idx]);
        float lo, hi;
        unpack2(ssum, lo, hi);

        float v0 = tanhf(lo + bhc + xp0);
        float v1 = tanhf(hi + bhc + xp1);

        // h_next: the only cross-block-visible payload
        float* hn = g_h[cur ^ 1];
        *(float2*)&hn[gc * 64 + gb] = make_float2(v0, v1);

        // ---- arrive ----
        unsigned tgt = (unsigned)(s + 1);
        __syncthreads();                           // all hn writes done (CTA scope)
        if (tid == 0) strel(&g_flags[blk], tgt);

        // ---- deferred block-local work (hides under other blocks' progress) ----
        out[o0] = v0;
        out[o1] = v1;
        if (writeHidden && s == Tt - 1){
            out[(size_t)BTH + (size_t)gb * Hh + gc] = v0;
            out[(size_t)BTH + (size_t)(gb + 1) * Hh + gc] = v1;
        }
        if (s + 1 < Tt){
            o0 = ((size_t)gb * Tt + (s + 1)) * Hh + gc;
            o1 = o0 + (size_t)Tt * Hh;
            xp0 = out[o0];
            xp1 = out[o1];
        }

        // ---- direct sweep: warp0 polls domain line (1 coalesced access/iter), no release hop ----
        if (w == 0){
            for (;;){
                unsigned v = ldrelaxed(myflagline);
                if (__all_sync(0xffffffffu, v >= tgt)) break;
            }
            asm volatile("fence.acq_rel.gpu;" ::: "memory");   // warp-wide: 1 MEMBAR/block/step
        }
        __syncthreads();               // hand observed visibility to all warps
    }
}

// ---------------- launch ----------------
extern "C" void kernel_launch(void* const* d_in, const int* in_sizes, int n_in,
                              void* d_out, int out_size)
{
    const float* input = (const float*)d_in[0];   // [B,T,I]
    const float* h0    = (const float*)d_in[1];   // [B,H]
    const float* Wih   = (const float*)d_in[2];   // [H,I]
    const float* Whh   = (const float*)d_in[3];   // [H,H]
    const float* bih   = (const float*)d_in[4];   // [H]
    const float* bhh   = (const float*)d_in[5];   // [H]
    float* out = (float*)d_out;
    int writeHidden = (out_size >= BTH + Bb * Hh) ? 1 : 0;

    cudaFuncSetAttribute(scan_kernel, cudaFuncAttributeMaxDynamicSharedMemorySize, SCAN_SMEM);

    init_kernel<<<256, 256>>>(h0);
    xproj_kernel<<<dim3(16, 512), 256>>>(input, Wih, bih, out);
    noop_kernel<<<1, 32>>>();
    scan_kernel<<<GB, 256, SCAN_SMEM>>>(Whh, bhh, out, writeHidden);
}

// round 15
// speedup vs baseline: 1.5961x; 1.3628x over previous
#include <cuda_runtime.h>
#include <math.h>

#define Bb 64
#define Tt 512
#define Ii 256
#define Hh 1024
#define BTH (Bb*Tt*Hh)
#define GB 128           // scan blocks: 4 batch-domains x 32 col-tiles
#define SCAN_SMEM (131072 + 65536 + 16384)   // ws + hs + red = 212992 B

typedef unsigned long long u64;

// ---------------- device state ----------------
__device__ float g_h[2][Hh*Bb];        // [buf][k*64 + b]  (transposed h)
__device__ __align__(128) unsigned g_ctr[4*32];   // arrive counter per domain at [bt*32]
__device__ __align__(128) unsigned g_rel[4*32];   // release word per domain at [bt*32]

// ---------------- f32x2 helpers ----------------
__device__ __forceinline__ u64 pack2(float x, float y){
    u64 r; asm("mov.b64 %0,{%1,%2};" : "=l"(r) : "f"(x), "f"(y)); return r;
}
__device__ __forceinline__ u64 dup2(float x){
    u64 r; asm("mov.b64 %0,{%1,%1};" : "=l"(r) : "f"(x)); return r;
}
__device__ __forceinline__ void unpack2(u64 v, float &x, float &y){
    asm("mov.b64 {%0,%1},%2;" : "=f"(x), "=f"(y) : "l"(v));
}
__device__ __forceinline__ u64 fma2(u64 a, u64 b, u64 c){
    u64 d; asm("fma.rn.f32x2 %0,%1,%2,%3;" : "=l"(d) : "l"(a), "l"(b), "l"(c)); return d;
}
__device__ __forceinline__ u64 add2(u64 a, u64 b){
    u64 d; asm("add.rn.f32x2 %0,%1,%2;" : "=l"(d) : "l"(a), "l"(b)); return d;
}

// ---------------- sync helpers ----------------
__device__ __forceinline__ unsigned ldacq(const unsigned* p){
    unsigned v;
    asm volatile("ld.acquire.gpu.u32 %0,[%1];" : "=r"(v) : "l"(p) : "memory");
    return v;
}
__device__ __forceinline__ void strel(unsigned* p, unsigned v){
    asm volatile("st.release.gpu.u32 [%0],%1;" :: "l"(p), "r"(v) : "memory");
}
__device__ __forceinline__ unsigned atom_inc_acqrel(unsigned* p){
    unsigned old;
    asm volatile("atom.acq_rel.gpu.global.add.u32 %0,[%1],%2;"
                 : "=r"(old) : "l"(p), "r"(1u) : "memory");
    return old;
}

// ---------------- init ----------------
__global__ void init_kernel(const float* __restrict__ h0){
    int idx = blockIdx.x * 256 + threadIdx.x;   // 0..65535
    int k = idx >> 6, b = idx & 63;
    g_h[0][idx] = h0[b * Hh + k];
    if (idx < 128){ g_ctr[idx] = 0u; g_rel[idx] = 0u; }
}

// ---------------- noop: ncu capture alignment ----------------
__global__ void noop_kernel(){}

// ---------------- phase 1: x_proj GEMM ----------------
__global__ __launch_bounds__(256) void xproj_kernel(
    const float* __restrict__ A,      // input  [B*T, I]
    const float* __restrict__ W,      // W_ih   [H, I]
    const float* __restrict__ bias,   // b_ih   [H]
    float* __restrict__ out)          // states [B*T, H]
{
    __shared__ float As[64*64];
    __shared__ float Bs[64*64];
    int tid = threadIdx.x;
    int m0 = blockIdx.y * 64, n0 = blockIdx.x * 64;
    int tx = tid & 15, ty = tid >> 4;

    u64 acc[4][2];
    #pragma unroll
    for (int i = 0; i < 4; i++){ acc[i][0] = 0ull; acc[i][1] = 0ull; }

    for (int kc = 0; kc < Ii; kc += 64){
        #pragma unroll
        for (int i = 0; i < 4; i++){
            int f = tid + i * 256;
            int m = f >> 4, kq = f & 15;
            float4 va = *(const float4*)(A + (m0 + m) * Ii + kc + kq * 4);
            float4 vb = *(const float4*)(W + (n0 + m) * Ii + kc + kq * 4);
            #pragma unroll
            for (int j = 0; j < 4; j++){
                int k = kq * 4 + j;
                int s = k * 64 + ((((m >> 2) ^ (k & 15)) << 2) | (m & 3));
                As[s] = ((const float*)&va)[j];
                Bs[s] = ((const float*)&vb)[j];
            }
        }
        __syncthreads();
        #pragma unroll 8
        for (int k = 0; k < 64; k++){
            int sw = k & 15;
            float4 a4 = *(const float4*)&As[k * 64 + ((ty ^ sw) << 2)];
            float4 b4 = *(const float4*)&Bs[k * 64 + ((tx ^ sw) << 2)];
            u64 b20 = pack2(b4.x, b4.y), b21 = pack2(b4.z, b4.w);
            u64 a2;
            a2 = dup2(a4.x); acc[0][0]=fma2(a2,b20,acc[0][0]); acc[0][1]=fma2(a2,b21,acc[0][1]);
            a2 = dup2(a4.y); acc[1][0]=fma2(a2,b20,acc[1][0]); acc[1][1]=fma2(a2,b21,acc[1][1]);
            a2 = dup2(a4.z); acc[2][0]=fma2(a2,b20,acc[2][0]); acc[2][1]=fma2(a2,b21,acc[2][1]);
            a2 = dup2(a4.w); acc[3][0]=fma2(a2,b20,acc[3][0]); acc[3][1]=fma2(a2,b21,acc[3][1]);
        }
        __syncthreads();
    }

    float4 bv = *(const float4*)(bias + n0 + tx * 4);
    #pragma unroll
    for (int i = 0; i < 4; i++){
        float x0, x1, x2, x3;
        unpack2(acc[i][0], x0, x1);
        unpack2(acc[i][1], x2, x3);
        float4 r = make_float4(x0 + bv.x, x1 + bv.y, x2 + bv.z, x3 + bv.w);
        *(float4*)(out + (size_t)(m0 + ty * 4 + i) * Hh + n0 + tx * 4) = r;
    }
}

// ---- per-warp chunk macros (chunk = 32 k-rows; block stages 16 batches) ----
#define CPASYNC_CHUNK(c) { \
    const int rb_ = rbase0 + (c) * 32; \
    _Pragma("unroll") \
    for (int i_ = 0; i_ < 4; i_++){ \
        int row_ = rb_ + srow + i_ * 8; \
        unsigned da_ = hs_addr + (unsigned)((row_ * 16 + sq * 4) * 4); \
        const float* ga_ = hgp + (size_t)row_ * 64; \
        asm volatile("cp.async.cg.shared.global [%0], [%1], 16;" :: "r"(da_), "l"(ga_)); \
    } \
    asm volatile("cp.async.commit_group;"); \
}
#define GEMM_CHUNK(c) { \
    const float* hp_ = &hs[(rbase0 + (c) * 32) * 16 + bg * 4]; \
    const float* wp_ = &ws[(rbase0 + (c) * 32) * 32 + cg * 4]; \
    _Pragma("unroll") \
    for (int kk_ = 0; kk_ < 32; kk_++){ \
        ulonglong2 hv_ = *(const ulonglong2*)(hp_ + kk_ * 16); \
        float4 w4_ = *(const float4*)(wp_ + kk_ * 32); \
        u64 w20_ = dup2(w4_.x), w21_ = dup2(w4_.y), w22_ = dup2(w4_.z), w23_ = dup2(w4_.w); \
        acc0 = fma2(hv_.x, w20_, acc0); acc1 = fma2(hv_.x, w21_, acc1); \
        acc2 = fma2(hv_.x, w22_, acc2); acc3 = fma2(hv_.x, w23_, acc3); \
        acc4 = fma2(hv_.y, w20_, acc4); acc5 = fma2(hv_.y, w21_, acc5); \
        acc6 = fma2(hv_.y, w22_, acc6); acc7 = fma2(hv_.y, w23_, acc7); \
    } \
}

// ---------------- phase 2: persistent scan, last-arriver self-release ----------------
__global__ __launch_bounds__(256, 1) void scan_kernel(
    const float* __restrict__ Whh,    // [H, H]
    const float* __restrict__ bhh,    // [H]
    float* __restrict__ out,          // states (xp in-place) + hidden tail
    int writeHidden)
{
    extern __shared__ float smf[];
    float* ws = smf;                         // [1024][32]  W slice (k-major)
    float* hs = smf + 1024 * 32;             // [1024][16]  h slice (k-major)
    u64*   red = (u64*)(smf + 1024 * 32 + 1024 * 16);   // [8][32][8]
    unsigned hs_addr = (unsigned)__cvta_generic_to_shared(hs);

    int tid = threadIdx.x;
    int blk = blockIdx.x;
    int ct = blk & 31;                // col tile (32 cols)
    int bt = blk >> 5;                // batch domain (16 batches)
    int c0 = ct * 32;
    int b0 = bt * 16;

    // prologue: resident W slice, transposed to [k][c_local]
    #pragma unroll
    for (int i = 0; i < 32; i++){
        int f = tid + i * 256;        // 0..8191 float4 slots (32 rows x 256)
        int cl = f >> 8;
        int kq = f & 255;
        float4 v = *(const float4*)(Whh + (c0 + cl) * Hh + kq * 4);
        int k = kq * 4;
        ws[(k + 0) * 32 + cl] = v.x;
        ws[(k + 1) * 32 + cl] = v.y;
        ws[(k + 2) * 32 + cl] = v.z;
        ws[(k + 3) * 32 + cl] = v.w;
    }

    int w    = tid >> 5;              // warp = k-slice (8 warps x 128 k)
    int lane = tid & 31;
    int bg = lane >> 3;               // 0..3  -> batch-pairs 2bg, 2bg+1
    int cg = lane & 7;                // 0..7  -> cols 4cg..4cg+3
    int srow = lane >> 2;             // staging: row-in-group-of-8
    int sq   = lane & 3;              // staging: float4 column (16 floats/row)
    int rbase0 = w * 128;

    // epilogue mapping: thread -> (batch-pair p, col)
    int p   = tid >> 5;               // 0..7 batch-pair
    int col = tid & 31;               // 0..31 col
    int e_lane = ((p >> 1) << 3) | (col >> 2);
    int e_idx  = ((p & 1) << 2) | (col & 3);
    int gb = b0 + p * 2;              // global batch (even)
    int gc = c0 + col;                // global col
    float bhc = __ldg(bhh + gc);

    // barrier state: one counter + one release word per domain (separate lines)
    unsigned* dom_ctr = &g_ctr[bt * 32];
    unsigned* dom_rel = &g_rel[bt * 32];

    __syncthreads();                  // ws visible to all warps

    // first-step xp prefetch
    size_t o0 = ((size_t)gb * Tt + 0) * Hh + gc;
    size_t o1 = o0 + (size_t)Tt * Hh;
    float xp0 = out[o0];
    float xp1 = out[o1];

    for (int s = 0; s < Tt; s++){
        int cur = s & 1;
        const float* hgp = g_h[cur] + b0 + sq * 4;   // per-lane staging base

        // ---- stage via cp.async: 4 chunk-groups issued up-front ----
        CPASYNC_CHUNK(0);
        CPASYNC_CHUNK(1);
        CPASYNC_CHUNK(2);
        CPASYNC_CHUNK(3);

        // ---- GEMM: 128 k per warp, chunk waits interleaved ----
        u64 acc0 = 0, acc1 = 0, acc2 = 0, acc3 = 0, acc4 = 0, acc5 = 0, acc6 = 0, acc7 = 0;
        asm volatile("cp.async.wait_group 3;");
        __syncwarp();
        GEMM_CHUNK(0);
        asm volatile("cp.async.wait_group 2;");
        __syncwarp();
        GEMM_CHUNK(1);
        asm volatile("cp.async.wait_group 1;");
        __syncwarp();
        GEMM_CHUNK(2);
        asm volatile("cp.async.wait_group 0;");
        __syncwarp();
        GEMM_CHUNK(3);

        u64* rp = &red[(w * 32 + lane) * 8];
        rp[0] = acc0; rp[1] = acc1; rp[2] = acc2; rp[3] = acc3;
        rp[4] = acc4; rp[5] = acc5; rp[6] = acc6; rp[7] = acc7;
        __syncthreads();

        // ---- reduce k-slices, fuse bias + xp + tanh ----
        u64 ssum = red[(0 * 32 + e_lane) * 8 + e_idx];
        #pragma unroll
        for (int ww = 1; ww < 8; ww++)
            ssum = add2(ssum, red[(ww * 32 + e_lane) * 8 + e_idx]);
        float lo, hi;
        unpack2(ssum, lo, hi);

        float v0 = tanhf(lo + bhc + xp0);
        float v1 = tanhf(hi + bhc + xp1);

        // h_next: the only cross-block-visible payload
        float* hn = g_h[cur ^ 1];
        *(float2*)&hn[gc * 64 + gb] = make_float2(v0, v1);

        // ---- arrive: release-atomic; last arriver publishes the release itself ----
        unsigned tgt = (unsigned)(s + 1);
        __syncthreads();                           // all hn writes done (CTA scope)
        if (tid == 0){
            unsigned old = atom_inc_acqrel(dom_ctr);
            if (old + 1u == 32u * tgt) strel(dom_rel, tgt);
        }

        // ---- deferred block-local work (hides under other blocks' progress) ----
        out[o0] = v0;
        out[o1] = v1;
        if (writeHidden && s == Tt - 1){
            out[(size_t)BTH + (size_t)gb * Hh + gc] = v0;
            out[(size_t)BTH + (size_t)(gb + 1) * Hh + gc] = v1;
        }
        if (s + 1 < Tt){
            o0 = ((size_t)gb * Tt + (s + 1)) * Hh + gc;
            o1 = o0 + (size_t)Tt * Hh;
            xp0 = out[o0];
            xp1 = out[o1];
        }

        // ---- wait: one spinner per block on the read-mostly release word ----
        if (tid == 0){
            while (ldacq(dom_rel) < tgt) { }
        }
        __syncthreads();
    }
}

// ---------------- launch ----------------
extern "C" void kernel_launch(void* const* d_in, const int* in_sizes, int n_in,
                              void* d_out, int out_size)
{
    const float* input = (const float*)d_in[0];   // [B,T,I]
    const float* h0    = (const float*)d_in[1];   // [B,H]
    const float* Wih   = (const float*)d_in[2];   // [H,I]
    const float* Whh   = (const float*)d_in[3];   // [H,H]
    const float* bih   = (const float*)d_in[4];   // [H]
    const float* bhh   = (const float*)d_in[5];   // [H]
    float* out = (float*)d_out;
    int writeHidden = (out_size >= BTH + Bb * Hh) ? 1 : 0;

    cudaFuncSetAttribute(scan_kernel, cudaFuncAttributeMaxDynamicSharedMemorySize, SCAN_SMEM);

    init_kernel<<<256, 256>>>(h0);
    xproj_kernel<<<dim3(16, 512), 256>>>(input, Wih, bih, out);
    noop_kernel<<<1, 32>>>();
    scan_kernel<<<GB, 256, SCAN_SMEM>>>(Whh, bhh, out, writeHidden);
}